// round 16
// baseline (speedup 1.0000x reference)
#include <cuda_runtime.h>
#include <cstdint>

// FINAL — FourierFFTLayer_13657996001424 on GB300 (sm_103a).
//
// reference = ifft(fft(x)).real on real fp32 input == identity up to fp32
// FFT roundoff (measured rel_err 1.3e-7 vs 1e-3 tolerance). Optimal kernel
// is a pure HBM-bandwidth-bound copy: 128 MB read + 128 MB write = 256 MB
// aggregate at ~7.5 TB/s (~94% of 8 TB/s spec), the chip's path-independent
// LTS ceiling — confirmed identical for SM-kernel, copy-engine, and all
// cache-policy paths.
//
// Design space exhaustively measured (15 rounds):
//   unroll x1/x2/x4/x8       -> U-curve, min at x2 (MLP vs occupancy)
//   SM kernel vs CE memcpy   -> SM wins (CE: costlier node replay)
//   flat vs persistent grid  -> flat wins (dynamic CLC load balancing
//                               beats static partition over per-SM
//                               speed variance, near/far L2 die)
//   stores .cs/default/.wt   -> .cs wins (clean drain, no dirty-L2
//                               contention across graph replays)
//   loads  .cs/.lu           -> .cs wins (.lu degraded kernel time/DRAM%)
//   block 128 vs 256         -> tie; 128 kept (finer granularity)
//
// Winner: MLP=2/thread, 128 threads x 32768 blocks, streaming .cs on both
// streams, guard-free fast path on the exact-divide shape.
// Kernel 35.8-36.2us (5 samples), dur ~43.5us.

__global__ __launch_bounds__(128) void identity_copy_f4x2_b128(
    const float4* __restrict__ in, float4* __restrict__ out, int n4)
{
    int base = blockIdx.x * (blockDim.x * 2) + threadIdx.x;
    const int s = blockDim.x;

    if (base + s < n4) {
        float4 a = __ldcs(in + base);
        float4 b = __ldcs(in + base + s);
        __stcs(out + base,     a);
        __stcs(out + base + s, b);
    } else {
        #pragma unroll
        for (int k = 0; k < 2; k++) {
            int i = base + k * s;
            if (i < n4) __stcs(out + i, __ldcs(in + i));
        }
    }
}

__global__ __launch_bounds__(256) void identity_copy_tail(
    const float* __restrict__ in, float* __restrict__ out, int start, int n)
{
    int i = start + blockIdx.x * blockDim.x + threadIdx.x;
    if (i < n) out[i] = in[i];
}

extern "C" void kernel_launch(void* const* d_in, const int* in_sizes, int n_in,
                              void* d_out, int out_size)
{
    const float* x = (const float*)d_in[0];
    float* out = (float*)d_out;
    int n = in_sizes[0];           // 33,554,432 (8 * 4096 * 1024)

    int n4 = n / 4;                // 8,388,608 float4
    if (n4 > 0) {
        const int threads = 128;
        const int per_block = threads * 2;             // 256 float4 / block
        int blocks = (n4 + per_block - 1) / per_block; // 32768
        identity_copy_f4x2_b128<<<blocks, threads>>>(
            (const float4*)x, (float4*)out, n4);
    }
    int tail_start = n4 * 4;
    if (n - tail_start > 0) {
        identity_copy_tail<<<1, 256>>>(x, out, tail_start, n);
    }
}

// round 17
// speedup vs baseline: 1.0235x; 1.0235x over previous
#include <cuda_runtime.h>
#include <cstdint>

// FourierFFTLayer == identity (ifft(fft(x)).real, rel_err ~1.3e-7 << 1e-3).
// HBM-bound copy at the ~7.5 TB/s path-independent LTS ceiling. This round
// probes Blackwell's 256-bit global accesses (ld/st.global.v8.f32 ->
// LDG.E.256/STG.E.256): halves LSU issue count and L1tex wavefront
// bookkeeping per byte. Shape otherwise the measured optimum: MLP=2/thread,
// .cs streaming policy both directions, 128-thread blocks.

__global__ __launch_bounds__(128) void identity_copy_v8x2(
    const float* __restrict__ in, float* __restrict__ out, int n8)
{
    // index in units of 8 floats (32 bytes)
    int base = blockIdx.x * (blockDim.x * 2) + threadIdx.x;
    const int s = blockDim.x;

    if (base + s < n8) {
        const float* p0 = in + (size_t)base * 8;
        const float* p1 = in + (size_t)(base + s) * 8;
        float a0,a1,a2,a3,a4,a5,a6,a7;
        float b0,b1,b2,b3,b4,b5,b6,b7;
        asm volatile("ld.global.cs.v8.f32 {%0,%1,%2,%3,%4,%5,%6,%7}, [%8];"
            : "=f"(a0),"=f"(a1),"=f"(a2),"=f"(a3),
              "=f"(a4),"=f"(a5),"=f"(a6),"=f"(a7) : "l"(p0));
        asm volatile("ld.global.cs.v8.f32 {%0,%1,%2,%3,%4,%5,%6,%7}, [%8];"
            : "=f"(b0),"=f"(b1),"=f"(b2),"=f"(b3),
              "=f"(b4),"=f"(b5),"=f"(b6),"=f"(b7) : "l"(p1));
        float* q0 = out + (size_t)base * 8;
        float* q1 = out + (size_t)(base + s) * 8;
        asm volatile("st.global.cs.v8.f32 [%8], {%0,%1,%2,%3,%4,%5,%6,%7};"
            :: "f"(a0),"f"(a1),"f"(a2),"f"(a3),
               "f"(a4),"f"(a5),"f"(a6),"f"(a7), "l"(q0) : "memory");
        asm volatile("st.global.cs.v8.f32 [%8], {%0,%1,%2,%3,%4,%5,%6,%7};"
            :: "f"(b0),"f"(b1),"f"(b2),"f"(b3),
               "f"(b4),"f"(b5),"f"(b6),"f"(b7), "l"(q1) : "memory");
    } else {
        #pragma unroll
        for (int k = 0; k < 2; k++) {
            int i = base + k * s;
            if (i < n8) {
                const float4* p = (const float4*)(in + (size_t)i * 8);
                float4* q = (float4*)(out + (size_t)i * 8);
                __stcs(q,     __ldcs(p));
                __stcs(q + 1, __ldcs(p + 1));
            }
        }
    }
}

__global__ __launch_bounds__(256) void identity_copy_tail(
    const float* __restrict__ in, float* __restrict__ out, int start, int n)
{
    int i = start + blockIdx.x * blockDim.x + threadIdx.x;
    if (i < n) out[i] = in[i];
}

extern "C" void kernel_launch(void* const* d_in, const int* in_sizes, int n_in,
                              void* d_out, int out_size)
{
    const float* x = (const float*)d_in[0];
    float* out = (float*)d_out;
    int n = in_sizes[0];           // 33,554,432 (8 * 4096 * 1024)

    int n8 = n / 8;                // 4,194,304 float8 groups
    if (n8 > 0) {
        const int threads = 128;
        const int per_block = threads * 2;             // 256 float8 / block
        int blocks = (n8 + per_block - 1) / per_block; // 16384
        identity_copy_v8x2<<<blocks, threads>>>(x, out, n8);
    }
    int tail_start = n8 * 8;
    if (n - tail_start > 0) {
        identity_copy_tail<<<1, 256>>>(x, out, tail_start, n);
    }
}